// round 4
// baseline (speedup 1.0000x reference)
#include <cuda_runtime.h>
#include <cuda_pipeline.h>

#define NH      32
#define HD      128
#define QLR     1536
#define BSZ     8
#define SEQ     4096
#define NQ      (NH*HD)            // 4096 q columns
#define NSPLIT  16
#define LOG2SPL 4
#define TOKS    (SEQ/NSPLIT)       // 256 tokens per work item
#define NWARP   8                  // warps per attention block
#define NITEMS  (BSZ*NH*NSPLIT)    // 4096 work items
#define GRID_AT (148*4)            // persistent attention grid
#define KTILES  16
#define KCHUNK  (QLR/KTILES)       // 96
#define LOG2E   1.4426950408889634f

// attention staging
#define STOK    16                          // tokens per stage
#define NSTAGE  3                           // pipeline depth
#define NSTG    (TOKS/STOK)                 // 16 stages per item
#define TOKB    ((size_t)NH * 1024)         // bytes between consecutive tokens
#define STAGEB  (STOK * 1024)               // 16 KB per stage
#define STAGEF4 (STOK * 64)                 // float4 per stage

// Scratch (device globals: no allocation allowed in kernel_launch)
__device__ float  g_qpart[KTILES][BSZ*NQ];      // split-K GEMM partials
__device__ float  g_q[BSZ*NQ];                  // q = h@W + b (log2e-scaled)
__device__ float  g_pacc[BSZ*NH*NSPLIT*HD];     // split-KV weighted-V partials
__device__ float2 g_pml[BSZ*NH*NSPLIT];         // (max, sumexp) per split (log2 domain)
__device__ int    g_work;                        // work-queue counter

// ---------------------------------------------------------------------------
// Kernel 1: split-K GEMM, float4 columns. grid (8, KTILES), block 128
// ---------------------------------------------------------------------------
__global__ void qgemm_kernel(const float* __restrict__ hq,
                             const float* __restrict__ W) {
    __shared__ float sh[BSZ][KCHUNK];
    const int k0 = blockIdx.y * KCHUNK;
    for (int idx = threadIdx.x; idx < BSZ * KCHUNK; idx += blockDim.x) {
        int b = idx / KCHUNK, k = idx % KCHUNK;
        sh[b][k] = hq[b * QLR + k0 + k];
    }
    __syncthreads();

    const int col4 = blockIdx.x * blockDim.x + threadIdx.x;
    const float4* W4 = (const float4*)W;

    float4 acc[BSZ];
#pragma unroll
    for (int b = 0; b < BSZ; b++) acc[b] = make_float4(0.f, 0.f, 0.f, 0.f);

#pragma unroll 8
    for (int k = 0; k < KCHUNK; k++) {
        float4 w = __ldg(&W4[(size_t)(k0 + k) * (NQ / 4) + col4]);
#pragma unroll
        for (int b = 0; b < BSZ; b++) {
            float s = sh[b][k];
            acc[b].x += w.x * s; acc[b].y += w.y * s;
            acc[b].z += w.z * s; acc[b].w += w.w * s;
        }
    }
#pragma unroll
    for (int b = 0; b < BSZ; b++)
        ((float4*)&g_qpart[blockIdx.y][b * NQ])[col4] = acc[b];
}

// ---------------------------------------------------------------------------
// Kernel 2: reduce split-K partials + bias into g_q (log2e-scaled).
// Also resets the attention work-queue counter.
// ---------------------------------------------------------------------------
__global__ void qreduce_kernel(const float* __restrict__ bq) {
    if (blockIdx.x == 0 && threadIdx.x == 0) g_work = 0;
    int i = blockIdx.x * blockDim.x + threadIdx.x;   // float4 index
    if (i >= BSZ * NQ / 4) return;
    const float4* b4 = (const float4*)bq;
    float4 s = b4[i & (NQ / 4 - 1)];
#pragma unroll
    for (int t = 0; t < KTILES; t++) {
        float4 p = ((const float4*)g_qpart[t])[i];
        s.x += p.x; s.y += p.y; s.z += p.z; s.w += p.w;
    }
    s.x *= LOG2E; s.y *= LOG2E; s.z *= LOG2E; s.w *= LOG2E;
    ((float4*)g_q)[i] = s;
}

// ---------------------------------------------------------------------------
// Kernel 3: persistent split-KV flash attention, atomic work queue,
// cp.async 3-stage SMEM pipeline (16 tokens / 16 KB per stage).
// Warp w consumes tokens {w, w+8} of each stage (ILP-2).
// ---------------------------------------------------------------------------
__global__ void __launch_bounds__(NWARP * 32)
attn_partial_kernel(const float* __restrict__ kv) {
    extern __shared__ float4 stage[];            // NSTAGE * STAGEF4 float4
    __shared__ int   s_item;
    __shared__ float s_acc[NWARP][HD];
    __shared__ float s_m[NWARP], s_l[NWARP];

    const int tid  = threadIdx.x;
    const int warp = tid >> 5;
    const int lane = tid & 31;
    const char* kvb = (const char*)kv;

    for (;;) {
        if (tid == 0) s_item = atomicAdd(&g_work, 1);
        __syncthreads();
        const int item = s_item;
        if (item >= NITEMS) break;

        const int split = item & (NSPLIT - 1);
        const int bh    = item >> LOG2SPL;    // b*NH + h
        const int h     = bh & (NH - 1);
        const int b     = bh >> 5;

        const float4 q4 = *(const float4*)&g_q[bh * HD + lane * 4];

        // byte base of this item's first token row (k||v = 1024 B)
        const size_t item_base =
            (((size_t)b * SEQ + (size_t)split * TOKS) * NH + h) * 1024;

        // ---- issue one stage of cp.async (16 KB = 1024 x 16B chunks) ----
        auto issue_stage = [&](int st) {
            const char* gsrc = kvb + item_base + (size_t)st * STOK * TOKB;
            float4* dst = stage + (st % NSTAGE) * STAGEF4;
#pragma unroll
            for (int r = 0; r < 4; r++) {
                int idx   = tid + r * 256;        // 0..1023
                int tok   = idx >> 6;
                int chunk = idx & 63;
                __pipeline_memcpy_async(
                    (char*)dst + tok * 1024 + chunk * 16,
                    gsrc + (size_t)tok * TOKB + chunk * 16, 16);
            }
        };

        issue_stage(0); __pipeline_commit();
        issue_stage(1); __pipeline_commit();

        float  m = -1e30f, l = 0.0f;
        float4 acc = make_float4(0.f, 0.f, 0.f, 0.f);

        for (int st = 0; st < NSTG; st++) {
            __pipeline_wait_prior(NSTAGE - 2);   // oldest stage landed
            __syncthreads();

            const float4* buf = stage + (st % NSTAGE) * STAGEF4;
            const float4* t0  = buf + warp * 64;              // token warp
            const float4* t1  = buf + (warp + 8) * 64;        // token warp+8

            float4 kc0 = t0[lane],      vc0 = t0[32 + lane];
            float4 kc1 = t1[lane],      vc1 = t1[32 + lane];

            float sc0 = kc0.x * q4.x + kc0.y * q4.y + kc0.z * q4.z + kc0.w * q4.w;
            float sc1 = kc1.x * q4.x + kc1.y * q4.y + kc1.z * q4.z + kc1.w * q4.w;
#pragma unroll
            for (int o = 16; o > 0; o >>= 1) {
                sc0 += __shfl_xor_sync(0xffffffffu, sc0, o);
                sc1 += __shfl_xor_sync(0xffffffffu, sc1, o);
            }
            float nm    = fmaxf(m, fmaxf(sc0, sc1));
            float scale = exp2f(m - nm);
            float p0    = exp2f(sc0 - nm);
            float p1    = exp2f(sc1 - nm);
            m = nm;
            l = l * scale + p0 + p1;
            acc.x = acc.x * scale + p0 * vc0.x + p1 * vc1.x;
            acc.y = acc.y * scale + p0 * vc0.y + p1 * vc1.y;
            acc.z = acc.z * scale + p0 * vc0.z + p1 * vc1.z;
            acc.w = acc.w * scale + p0 * vc0.w + p1 * vc1.w;

            __syncthreads();                     // stage fully consumed
            if (st + 2 < NSTG) issue_stage(st + 2);
            __pipeline_commit();                 // always commit (may be empty)
        }

        // merge the NWARP per-warp partial softmaxes
        s_acc[warp][lane * 4 + 0] = acc.x;
        s_acc[warp][lane * 4 + 1] = acc.y;
        s_acc[warp][lane * 4 + 2] = acc.z;
        s_acc[warp][lane * 4 + 3] = acc.w;
        if (lane == 0) { s_m[warp] = m; s_l[warp] = l; }
        __syncthreads();

        float M = -1e30f;
#pragma unroll
        for (int w = 0; w < NWARP; w++) M = fmaxf(M, s_m[w]);
        float L = 0.0f;
#pragma unroll
        for (int w = 0; w < NWARP; w++) L += exp2f(s_m[w] - M) * s_l[w];

        const int d = tid;
        if (d < HD) {
            float a = 0.0f;
#pragma unroll
            for (int w = 0; w < NWARP; w++) a += exp2f(s_m[w] - M) * s_acc[w][d];
            g_pacc[(bh * NSPLIT + split) * HD + d] = a;
        }
        if (tid == 0)
            g_pml[bh * NSPLIT + split] = make_float2(M, L);

        __syncthreads();   // protect s_item / s_* reuse across items
    }
}

// ---------------------------------------------------------------------------
// Kernel 4: combine split partials -> output. Flattened: one thread per
// (bh, d) element; 16 independent loads in flight per thread.
// ---------------------------------------------------------------------------
__global__ void attn_combine_kernel(float* __restrict__ out) {
    const int gid = blockIdx.x * blockDim.x + threadIdx.x;  // 0..32767
    const int bh  = gid >> 7;
    const int d   = gid & (HD - 1);

    float2 ml[NSPLIT];
#pragma unroll
    for (int i = 0; i < NSPLIT; i++) ml[i] = __ldg(&g_pml[bh * NSPLIT + i]);

    float M = -1e30f;
#pragma unroll
    for (int i = 0; i < NSPLIT; i++) M = fmaxf(M, ml[i].x);
    float L = 0.0f;
#pragma unroll
    for (int i = 0; i < NSPLIT; i++) L += exp2f(ml[i].x - M) * ml[i].y;

    float pa[NSPLIT];
#pragma unroll
    for (int i = 0; i < NSPLIT; i++)
        pa[i] = __ldg(&g_pacc[(bh * NSPLIT + i) * HD + d]);

    float a = 0.0f;
#pragma unroll
    for (int i = 0; i < NSPLIT; i++) a += exp2f(ml[i].x - M) * pa[i];

    out[bh * HD + d] = a / L;
}

// ---------------------------------------------------------------------------
extern "C" void kernel_launch(void* const* d_in, const int* in_sizes, int n_in,
                              void* d_out, int out_size) {
    const float* hq = (const float*)d_in[0];   // (8, 1536)
    const float* kv = (const float*)d_in[1];   // (8, 4096, 32, 256)
    const float* W  = (const float*)d_in[2];   // (1536, 4096)
    const float* bq = (const float*)d_in[3];   // (4096,)
    float* out = (float*)d_out;                // (8, 4096)

    cudaFuncSetAttribute(attn_partial_kernel,
                         cudaFuncAttributeMaxDynamicSharedMemorySize,
                         NSTAGE * STAGEB);

    qgemm_kernel<<<dim3(NQ / 4 / 128, KTILES), 128>>>(hq, W);
    qreduce_kernel<<<(BSZ * NQ / 4 + 255) / 256, 256>>>(bq);
    attn_partial_kernel<<<GRID_AT, NWARP * 32, NSTAGE * STAGEB>>>(kv);
    attn_combine_kernel<<<BSZ * NQ / 256, 256>>>(out);
}

// round 5
// speedup vs baseline: 1.1164x; 1.1164x over previous
#include <cuda_runtime.h>

#define NH      32
#define HD      128
#define QLR     1536
#define BSZ     8
#define SEQ     4096
#define NQ      (NH*HD)            // 4096 q columns
#define NSPLIT  16
#define LOG2SPL 4
#define TOKS    (SEQ/NSPLIT)       // 256 tokens per work item
#define NWARP   8                  // warps per attention block
#define NPAIR   (TOKS/(2*NWARP))   // 16 pair-iterations per warp
#define NITEMS  (BSZ*NH*NSPLIT)    // 4096 work items
#define GRID_AT (148*3)            // persistent attention grid (3 blocks/SM)
#define KTILES  16
#define KCHUNK  (QLR/KTILES)       // 96
#define LOG2E   1.4426950408889634f
#define TOKF4   ((size_t)NH * 64)  // float4 stride between consecutive tokens
#define DEPTH   3                  // prefetch depth in token-pairs

// Scratch (device globals: no allocation allowed in kernel_launch)
__device__ float  g_qpart[KTILES][BSZ*NQ];      // split-K GEMM partials
__device__ float  g_q[BSZ*NQ];                  // q = h@W + b (log2e-scaled)
__device__ float  g_pacc[BSZ*NH*NSPLIT*HD];     // split-KV weighted-V partials
__device__ float2 g_pml[BSZ*NH*NSPLIT];         // (max, sumexp) per split (log2 domain)
__device__ int    g_work;                        // work-queue counter

// ---------------------------------------------------------------------------
// Kernel 1: split-K GEMM, float4 columns. grid (8, KTILES), block 128
// ---------------------------------------------------------------------------
__global__ void qgemm_kernel(const float* __restrict__ hq,
                             const float* __restrict__ W) {
    __shared__ float sh[BSZ][KCHUNK];
    const int k0 = blockIdx.y * KCHUNK;
    for (int idx = threadIdx.x; idx < BSZ * KCHUNK; idx += blockDim.x) {
        int b = idx / KCHUNK, k = idx % KCHUNK;
        sh[b][k] = hq[b * QLR + k0 + k];
    }
    __syncthreads();

    const int col4 = blockIdx.x * blockDim.x + threadIdx.x;
    const float4* W4 = (const float4*)W;

    float4 acc[BSZ];
#pragma unroll
    for (int b = 0; b < BSZ; b++) acc[b] = make_float4(0.f, 0.f, 0.f, 0.f);

#pragma unroll 8
    for (int k = 0; k < KCHUNK; k++) {
        float4 w = __ldg(&W4[(size_t)(k0 + k) * (NQ / 4) + col4]);
#pragma unroll
        for (int b = 0; b < BSZ; b++) {
            float s = sh[b][k];
            acc[b].x += w.x * s; acc[b].y += w.y * s;
            acc[b].z += w.z * s; acc[b].w += w.w * s;
        }
    }
#pragma unroll
    for (int b = 0; b < BSZ; b++)
        ((float4*)&g_qpart[blockIdx.y][b * NQ])[col4] = acc[b];
}

// ---------------------------------------------------------------------------
// Kernel 2: reduce split-K partials + bias into g_q (log2e-scaled).
// Also resets the attention work-queue counter.
// ---------------------------------------------------------------------------
__global__ void qreduce_kernel(const float* __restrict__ bq) {
    if (blockIdx.x == 0 && threadIdx.x == 0) g_work = 0;
    int i = blockIdx.x * blockDim.x + threadIdx.x;   // float4 index
    if (i >= BSZ * NQ / 4) return;
    const float4* b4 = (const float4*)bq;
    float4 s = b4[i & (NQ / 4 - 1)];
#pragma unroll
    for (int t = 0; t < KTILES; t++) {
        float4 p = ((const float4*)g_qpart[t])[i];
        s.x += p.x; s.y += p.y; s.z += p.z; s.w += p.w;
    }
    s.x *= LOG2E; s.y *= LOG2E; s.z *= LOG2E; s.w *= LOG2E;
    ((float4*)g_q)[i] = s;
}

// ---------------------------------------------------------------------------
// Kernel 3: persistent split-KV flash attention, atomic work queue.
// Warp-per-token-pair with DEPTH=3 ring prefetch: 12 LDG.128 in flight
// per warp (~144 KB/SM at 3 blocks/SM).
// kv row for (b,s,h) is 64 float4: [0:32)=key, [32:64)=value.
// ---------------------------------------------------------------------------
__global__ void __launch_bounds__(NWARP * 32, 3)
attn_partial_kernel(const float* __restrict__ kv) {
    __shared__ int   s_item;
    __shared__ float s_acc[NWARP][HD];
    __shared__ float s_m[NWARP], s_l[NWARP];

    const int warp = threadIdx.x >> 5;
    const int lane = threadIdx.x & 31;
    const float4* kv4 = (const float4*)kv;

    for (;;) {
        if (threadIdx.x == 0) s_item = atomicAdd(&g_work, 1);
        __syncthreads();
        const int item = s_item;
        if (item >= NITEMS) break;

        const int split = item & (NSPLIT - 1);
        const int bh    = item >> LOG2SPL;    // b*NH + h
        const int h     = bh & (NH - 1);
        const int b     = bh >> 5;

        // q fragment (already log2e-scaled): lane holds q[lane*4..+3]
        const float4 q4 = *(const float4*)&g_q[bh * HD + lane * 4];

        float  m = -1e30f, l = 0.0f;
        float4 acc = make_float4(0.f, 0.f, 0.f, 0.f);

        // warp handles token pairs (s, s+1), pair stride 2*NWARP tokens
        const int s0 = split * TOKS + warp * 2;
        size_t base = (((size_t)b * SEQ + s0) * NH + h) * 64;
        const size_t PSTRIDE = (size_t)(2 * NWARP) * TOKF4;

        float4 kb[DEPTH][2], vb[DEPTH][2];
#pragma unroll
        for (int i = 0; i < DEPTH; i++) {
            kb[i][0] = __ldg(&kv4[base + lane]);
            vb[i][0] = __ldg(&kv4[base + 32 + lane]);
            kb[i][1] = __ldg(&kv4[base + TOKF4 + lane]);
            vb[i][1] = __ldg(&kv4[base + TOKF4 + 32 + lane]);
            base += PSTRIDE;
        }

#pragma unroll
        for (int p = 0; p < NPAIR; p++) {
            const int slot = p % DEPTH;
            float4 kc0 = kb[slot][0], vc0 = vb[slot][0];
            float4 kc1 = kb[slot][1], vc1 = vb[slot][1];
            if (p + DEPTH < NPAIR) {
                kb[slot][0] = __ldg(&kv4[base + lane]);
                vb[slot][0] = __ldg(&kv4[base + 32 + lane]);
                kb[slot][1] = __ldg(&kv4[base + TOKF4 + lane]);
                vb[slot][1] = __ldg(&kv4[base + TOKF4 + 32 + lane]);
                base += PSTRIDE;
            }
            float sc0 = kc0.x * q4.x + kc0.y * q4.y + kc0.z * q4.z + kc0.w * q4.w;
            float sc1 = kc1.x * q4.x + kc1.y * q4.y + kc1.z * q4.z + kc1.w * q4.w;
#pragma unroll
            for (int o = 16; o > 0; o >>= 1) {
                sc0 += __shfl_xor_sync(0xffffffffu, sc0, o);
                sc1 += __shfl_xor_sync(0xffffffffu, sc1, o);
            }
            float nm    = fmaxf(m, fmaxf(sc0, sc1));
            float scale = exp2f(m - nm);
            float p0    = exp2f(sc0 - nm);
            float p1    = exp2f(sc1 - nm);
            m = nm;
            l = l * scale + p0 + p1;
            acc.x = acc.x * scale + p0 * vc0.x + p1 * vc1.x;
            acc.y = acc.y * scale + p0 * vc0.y + p1 * vc1.y;
            acc.z = acc.z * scale + p0 * vc0.z + p1 * vc1.z;
            acc.w = acc.w * scale + p0 * vc0.w + p1 * vc1.w;
        }

        // merge the NWARP per-warp partial softmaxes
        s_acc[warp][lane * 4 + 0] = acc.x;
        s_acc[warp][lane * 4 + 1] = acc.y;
        s_acc[warp][lane * 4 + 2] = acc.z;
        s_acc[warp][lane * 4 + 3] = acc.w;
        if (lane == 0) { s_m[warp] = m; s_l[warp] = l; }
        __syncthreads();

        float M = -1e30f;
#pragma unroll
        for (int w = 0; w < NWARP; w++) M = fmaxf(M, s_m[w]);
        float L = 0.0f;
#pragma unroll
        for (int w = 0; w < NWARP; w++) L += exp2f(s_m[w] - M) * s_l[w];

        const int d = threadIdx.x;
        if (d < HD) {
            float a = 0.0f;
#pragma unroll
            for (int w = 0; w < NWARP; w++) a += exp2f(s_m[w] - M) * s_acc[w][d];
            g_pacc[(bh * NSPLIT + split) * HD + d] = a;
        }
        if (threadIdx.x == 0)
            g_pml[bh * NSPLIT + split] = make_float2(M, L);

        __syncthreads();   // protect s_item / s_* reuse across items
    }
}

// ---------------------------------------------------------------------------
// Kernel 4: combine split partials -> output. One thread per (bh, d).
// ---------------------------------------------------------------------------
__global__ void attn_combine_kernel(float* __restrict__ out) {
    const int gid = blockIdx.x * blockDim.x + threadIdx.x;  // 0..32767
    const int bh  = gid >> 7;
    const int d   = gid & (HD - 1);

    float2 ml[NSPLIT];
#pragma unroll
    for (int i = 0; i < NSPLIT; i++) ml[i] = __ldg(&g_pml[bh * NSPLIT + i]);

    float M = -1e30f;
#pragma unroll
    for (int i = 0; i < NSPLIT; i++) M = fmaxf(M, ml[i].x);
    float L = 0.0f;
#pragma unroll
    for (int i = 0; i < NSPLIT; i++) L += exp2f(ml[i].x - M) * ml[i].y;

    float pa[NSPLIT];
#pragma unroll
    for (int i = 0; i < NSPLIT; i++)
        pa[i] = __ldg(&g_pacc[(bh * NSPLIT + i) * HD + d]);

    float a = 0.0f;
#pragma unroll
    for (int i = 0; i < NSPLIT; i++) a += exp2f(ml[i].x - M) * pa[i];

    out[bh * HD + d] = a / L;
}

// ---------------------------------------------------------------------------
extern "C" void kernel_launch(void* const* d_in, const int* in_sizes, int n_in,
                              void* d_out, int out_size) {
    const float* hq = (const float*)d_in[0];   // (8, 1536)
    const float* kv = (const float*)d_in[1];   // (8, 4096, 32, 256)
    const float* W  = (const float*)d_in[2];   // (1536, 4096)
    const float* bq = (const float*)d_in[3];   // (4096,)
    float* out = (float*)d_out;                // (8, 4096)

    qgemm_kernel<<<dim3(NQ / 4 / 128, KTILES), 128>>>(hq, W);
    qreduce_kernel<<<(BSZ * NQ / 4 + 255) / 256, 256>>>(bq);
    attn_partial_kernel<<<GRID_AT, NWARP * 32>>>(kv);
    attn_combine_kernel<<<BSZ * NQ / 256, 256>>>(out);
}

// round 8
// speedup vs baseline: 1.1541x; 1.0338x over previous
#include <cuda_runtime.h>

#define NH      32
#define HD      128
#define QLR     1536
#define BSZ     8
#define SEQ     4096
#define NQ      (NH*HD)            // 4096 q columns
#define NSPLIT  16
#define LOG2SPL 4
#define TOKS    (SEQ/NSPLIT)       // 256 tokens per work item
#define NWARP   8                  // warps per attention block
#define NPAIR   (TOKS/(2*NWARP))   // 16 pair-iterations per warp
#define NITEMS  (BSZ*NH*NSPLIT)    // 4096 work items
#define GRID_AT (148*3)            // persistent attention grid (3 blocks/SM)
#define KTILES  32
#define KCHUNK  (QLR/KTILES)       // 48
#define LOG2E   1.4426950408889634f
#define TOKF4   ((size_t)NH * 64)  // float4 stride between consecutive tokens
#define DEPTH   3                  // prefetch depth in token-pairs

// Scratch (device globals: no allocation allowed in kernel_launch)
__device__ float  g_qpart[KTILES][BSZ*NQ];      // split-K GEMM partials
__device__ float  g_q[BSZ*NQ];                  // q = h@W + b (log2e-scaled)
__device__ float  g_pacc[BSZ*NH*NSPLIT*HD];     // split-KV weighted-V partials
__device__ float2 g_pml[BSZ*NH*NSPLIT];         // (max, sumexp) per split (log2 domain)
__device__ int    g_work;                        // work-queue counter
__device__ int    g_done[BSZ*NH];                // per-bh completed-split counters

// ---------------------------------------------------------------------------
// Kernel 1: split-K GEMM, float4 columns. grid (8, KTILES=32), block 128
// ---------------------------------------------------------------------------
__global__ void qgemm_kernel(const float* __restrict__ hq,
                             const float* __restrict__ W) {
    __shared__ float sh[BSZ][KCHUNK];
    const int k0 = blockIdx.y * KCHUNK;
    for (int idx = threadIdx.x; idx < BSZ * KCHUNK; idx += blockDim.x) {
        int b = idx / KCHUNK, k = idx % KCHUNK;
        sh[b][k] = hq[b * QLR + k0 + k];
    }
    __syncthreads();

    const int col4 = blockIdx.x * blockDim.x + threadIdx.x;
    const float4* W4 = (const float4*)W;

    float4 acc[BSZ];
#pragma unroll
    for (int b = 0; b < BSZ; b++) acc[b] = make_float4(0.f, 0.f, 0.f, 0.f);

#pragma unroll 8
    for (int k = 0; k < KCHUNK; k++) {
        float4 w = __ldg(&W4[(size_t)(k0 + k) * (NQ / 4) + col4]);
#pragma unroll
        for (int b = 0; b < BSZ; b++) {
            float s = sh[b][k];
            acc[b].x += w.x * s; acc[b].y += w.y * s;
            acc[b].z += w.z * s; acc[b].w += w.w * s;
        }
    }
#pragma unroll
    for (int b = 0; b < BSZ; b++)
        ((float4*)&g_qpart[blockIdx.y][b * NQ])[col4] = acc[b];
}

// ---------------------------------------------------------------------------
// Kernel 2: reduce split-K partials + bias into g_q (log2e-scaled).
// Also resets the work-queue and completion counters (graph-replay safe).
// ---------------------------------------------------------------------------
__global__ void qreduce_kernel(const float* __restrict__ bq) {
    if (blockIdx.x == 0) {
        if (threadIdx.x == 0) g_work = 0;
        if (threadIdx.x < BSZ * NH) g_done[threadIdx.x] = 0;
    }
    int i = blockIdx.x * blockDim.x + threadIdx.x;   // float4 index
    if (i >= BSZ * NQ / 4) return;
    const float4* b4 = (const float4*)bq;
    float4 s = b4[i & (NQ / 4 - 1)];
#pragma unroll
    for (int t = 0; t < KTILES; t++) {
        float4 p = ((const float4*)g_qpart[t])[i];
        s.x += p.x; s.y += p.y; s.z += p.z; s.w += p.w;
    }
    s.x *= LOG2E; s.y *= LOG2E; s.z *= LOG2E; s.w *= LOG2E;
    ((float4*)g_q)[i] = s;
}

// ---------------------------------------------------------------------------
// Kernel 3: persistent split-KV flash attention + fused combine.
// Atomic work queue; warp-per-token-pair with DEPTH=3 ring prefetch.
// The block that finishes the last split of a bh combines all 16 splits
// (reads hit L2) and writes the final output row. No cross-block waiting:
// exactly one block observes count==NSPLIT-1 and it already holds fresh data
// behind the release fences of all 16 writers.
// ---------------------------------------------------------------------------
__global__ void __launch_bounds__(NWARP * 32, 3)
attn_partial_kernel(const float* __restrict__ kv, float* __restrict__ out) {
    __shared__ int   s_item;
    __shared__ int   s_last;
    __shared__ float s_acc[NWARP][HD];
    __shared__ float s_m[NWARP], s_l[NWARP];

    const int warp = threadIdx.x >> 5;
    const int lane = threadIdx.x & 31;
    const float4* kv4 = (const float4*)kv;

    for (;;) {
        if (threadIdx.x == 0) s_item = atomicAdd(&g_work, 1);
        __syncthreads();
        const int item = s_item;
        if (item >= NITEMS) break;

        const int split = item & (NSPLIT - 1);
        const int bh    = item >> LOG2SPL;    // b*NH + h
        const int h     = bh & (NH - 1);
        const int b     = bh >> 5;

        // q fragment (already log2e-scaled): lane holds q[lane*4..+3]
        const float4 q4 = *(const float4*)&g_q[bh * HD + lane * 4];

        float  m = -1e30f, l = 0.0f;
        float4 acc = make_float4(0.f, 0.f, 0.f, 0.f);

        // warp handles token pairs (s, s+1), pair stride 2*NWARP tokens
        const int s0 = split * TOKS + warp * 2;
        size_t base = (((size_t)b * SEQ + s0) * NH + h) * 64;
        const size_t PSTRIDE = (size_t)(2 * NWARP) * TOKF4;

        float4 kb[DEPTH][2], vb[DEPTH][2];
#pragma unroll
        for (int i = 0; i < DEPTH; i++) {
            kb[i][0] = __ldg(&kv4[base + lane]);
            vb[i][0] = __ldg(&kv4[base + 32 + lane]);
            kb[i][1] = __ldg(&kv4[base + TOKF4 + lane]);
            vb[i][1] = __ldg(&kv4[base + TOKF4 + 32 + lane]);
            base += PSTRIDE;
        }

#pragma unroll
        for (int p = 0; p < NPAIR; p++) {
            const int slot = p % DEPTH;
            float4 kc0 = kb[slot][0], vc0 = vb[slot][0];
            float4 kc1 = kb[slot][1], vc1 = vb[slot][1];
            if (p + DEPTH < NPAIR) {
                kb[slot][0] = __ldg(&kv4[base + lane]);
                vb[slot][0] = __ldg(&kv4[base + 32 + lane]);
                kb[slot][1] = __ldg(&kv4[base + TOKF4 + lane]);
                vb[slot][1] = __ldg(&kv4[base + TOKF4 + 32 + lane]);
                base += PSTRIDE;
            }
            float sc0 = kc0.x * q4.x + kc0.y * q4.y + kc0.z * q4.z + kc0.w * q4.w;
            float sc1 = kc1.x * q4.x + kc1.y * q4.y + kc1.z * q4.z + kc1.w * q4.w;
#pragma unroll
            for (int o = 16; o > 0; o >>= 1) {
                sc0 += __shfl_xor_sync(0xffffffffu, sc0, o);
                sc1 += __shfl_xor_sync(0xffffffffu, sc1, o);
            }
            float nm    = fmaxf(m, fmaxf(sc0, sc1));
            float scale = exp2f(m - nm);
            float p0    = exp2f(sc0 - nm);
            float p1    = exp2f(sc1 - nm);
            m = nm;
            l = l * scale + p0 + p1;
            acc.x = acc.x * scale + p0 * vc0.x + p1 * vc1.x;
            acc.y = acc.y * scale + p0 * vc0.y + p1 * vc1.y;
            acc.z = acc.z * scale + p0 * vc0.z + p1 * vc1.z;
            acc.w = acc.w * scale + p0 * vc0.w + p1 * vc1.w;
        }

        // merge the NWARP per-warp partial softmaxes
        s_acc[warp][lane * 4 + 0] = acc.x;
        s_acc[warp][lane * 4 + 1] = acc.y;
        s_acc[warp][lane * 4 + 2] = acc.z;
        s_acc[warp][lane * 4 + 3] = acc.w;
        if (lane == 0) { s_m[warp] = m; s_l[warp] = l; }
        __syncthreads();

        float M = -1e30f;
#pragma unroll
        for (int w = 0; w < NWARP; w++) M = fmaxf(M, s_m[w]);
        float L = 0.0f;
#pragma unroll
        for (int w = 0; w < NWARP; w++) L += exp2f(s_m[w] - M) * s_l[w];

        const int d = threadIdx.x;
        if (d < HD) {
            float a = 0.0f;
#pragma unroll
            for (int w = 0; w < NWARP; w++) a += exp2f(s_m[w] - M) * s_acc[w][d];
            g_pacc[(bh * NSPLIT + split) * HD + d] = a;
        }
        if (threadIdx.x == 0)
            g_pml[bh * NSPLIT + split] = make_float2(M, L);

        // ---- completion protocol: release our partials, count splits ----
        __threadfence();                     // release (all writers fence)
        __syncthreads();
        if (threadIdx.x == 0)
            s_last = (atomicAdd(&g_done[bh], 1) == NSPLIT - 1);
        __syncthreads();

        if (s_last) {
            // we finished the last split of this bh: combine (L2-hot reads)
            __threadfence();                 // acquire
            if (threadIdx.x < HD) {
                float2 ml[NSPLIT];
#pragma unroll
                for (int i = 0; i < NSPLIT; i++)
                    ml[i] = __ldg(&g_pml[bh * NSPLIT + i]);
                float Mg = -1e30f;
#pragma unroll
                for (int i = 0; i < NSPLIT; i++) Mg = fmaxf(Mg, ml[i].x);
                float Lg = 0.0f;
#pragma unroll
                for (int i = 0; i < NSPLIT; i++)
                    Lg += exp2f(ml[i].x - Mg) * ml[i].y;

                float pa[NSPLIT];
#pragma unroll
                for (int i = 0; i < NSPLIT; i++)
                    pa[i] = __ldg(&g_pacc[(bh * NSPLIT + i) * HD + threadIdx.x]);
                float a = 0.0f;
#pragma unroll
                for (int i = 0; i < NSPLIT; i++)
                    a += exp2f(ml[i].x - Mg) * pa[i];

                out[bh * HD + threadIdx.x] = a / Lg;
            }
        }
        __syncthreads();   // protect s_item / s_* / s_last reuse across items
    }
}

// ---------------------------------------------------------------------------
extern "C" void kernel_launch(void* const* d_in, const int* in_sizes, int n_in,
                              void* d_out, int out_size) {
    const float* hq = (const float*)d_in[0];   // (8, 1536)
    const float* kv = (const float*)d_in[1];   // (8, 4096, 32, 256)
    const float* W  = (const float*)d_in[2];   // (1536, 4096)
    const float* bq = (const float*)d_in[3];   // (4096,)
    float* out = (float*)d_out;                // (8, 4096)

    qgemm_kernel<<<dim3(NQ / 4 / 128, KTILES), 128>>>(hq, W);
    qreduce_kernel<<<(BSZ * NQ / 4 + 255) / 256, 256>>>(bq);
    attn_partial_kernel<<<GRID_AT, NWARP * 32>>>(kv, out);
}